// round 8
// baseline (speedup 1.0000x reference)
#include <cuda_runtime.h>
#include <math.h>

// ============================================================================
// SpectralDiscrepancyModule — full fp32 pipeline.
// B=4096, H=1024, HALF=512, NCOMP=8, 3 pairs, 5 power-iteration steps.
// ============================================================================

#define BD   4096
#define HD   1024
#define HF   512
#define NC   8

// ------------------------- device scratch (no runtime alloc allowed) -------
__device__ float g_P[3][BD * HF];        // normalized projections   (24 MB)
__device__ float g_A[3][BD * BD];        // 1 - sigmoid(Pa Pb^T)     (192 MB)
__device__ float g_d[3][BD];             // deg^{-1/2}
__device__ float g_V[3][BD * NC];        // current eigvec block (Q)
__device__ float g_X[3][BD * NC];        // d ⊙ V
__device__ float g_LV[3][BD * NC];       // L @ V (QR workspace)

// ============================================================================
// NT-GEMM: C[i,j] = sum_k A[i,k]*B[j,k]   (both row-major)
// 128x128x16 tile, 256 threads, 8x8 register microtile.
// M,N multiples of 128; K multiple of 16.
// mode 0: C += bias[j];   mode 1: C = 1 - sigmoid(C) = 1/(1+exp(C))
// ============================================================================
__device__ __forceinline__ void gemm_nt(const float* __restrict__ Ag,
                                        const float* __restrict__ Bg,
                                        float* __restrict__ Cg,
                                        const float* __restrict__ bias,
                                        int N, int K, int mode) {
    __shared__ float As[16][128];
    __shared__ float Bs[16][128];
    const int tid  = threadIdx.x;
    const int m0   = blockIdx.y * 128;
    const int n0   = blockIdx.x * 128;
    const int lrow = tid >> 1;
    const int lcol = (tid & 1) << 3;
    const int tm   = (tid >> 4) << 3;
    const int tn   = (tid & 15) << 3;

    float acc[8][8];
#pragma unroll
    for (int i = 0; i < 8; i++)
#pragma unroll
        for (int j = 0; j < 8; j++) acc[i][j] = 0.f;

    const float* Ap = Ag + (size_t)(m0 + lrow) * K + lcol;
    const float* Bp = Bg + (size_t)(n0 + lrow) * K + lcol;

    for (int kt = 0; kt < K; kt += 16) {
        float4 a0 = *(const float4*)(Ap + kt);
        float4 a1 = *(const float4*)(Ap + kt + 4);
        float4 b0 = *(const float4*)(Bp + kt);
        float4 b1 = *(const float4*)(Bp + kt + 4);
        __syncthreads();
        As[lcol + 0][lrow] = a0.x; As[lcol + 1][lrow] = a0.y;
        As[lcol + 2][lrow] = a0.z; As[lcol + 3][lrow] = a0.w;
        As[lcol + 4][lrow] = a1.x; As[lcol + 5][lrow] = a1.y;
        As[lcol + 6][lrow] = a1.z; As[lcol + 7][lrow] = a1.w;
        Bs[lcol + 0][lrow] = b0.x; Bs[lcol + 1][lrow] = b0.y;
        Bs[lcol + 2][lrow] = b0.z; Bs[lcol + 3][lrow] = b0.w;
        Bs[lcol + 4][lrow] = b1.x; Bs[lcol + 5][lrow] = b1.y;
        Bs[lcol + 6][lrow] = b1.z; Bs[lcol + 7][lrow] = b1.w;
        __syncthreads();
#pragma unroll
        for (int k = 0; k < 16; k++) {
            float4 ra0 = *(const float4*)&As[k][tm];
            float4 ra1 = *(const float4*)&As[k][tm + 4];
            float4 rb0 = *(const float4*)&Bs[k][tn];
            float4 rb1 = *(const float4*)&Bs[k][tn + 4];
            float ra[8] = {ra0.x, ra0.y, ra0.z, ra0.w, ra1.x, ra1.y, ra1.z, ra1.w};
            float rb[8] = {rb0.x, rb0.y, rb0.z, rb0.w, rb1.x, rb1.y, rb1.z, rb1.w};
#pragma unroll
            for (int i = 0; i < 8; i++)
#pragma unroll
                for (int j = 0; j < 8; j++) acc[i][j] += ra[i] * rb[j];
        }
    }
#pragma unroll
    for (int i = 0; i < 8; i++) {
        size_t row = (size_t)(m0 + tm + i);
#pragma unroll
        for (int jb = 0; jb < 2; jb++) {
            int col = n0 + tn + jb * 4;
            float4 v;
            v.x = acc[i][jb * 4 + 0]; v.y = acc[i][jb * 4 + 1];
            v.z = acc[i][jb * 4 + 2]; v.w = acc[i][jb * 4 + 3];
            if (mode == 0) {
                v.x += bias[col + 0]; v.y += bias[col + 1];
                v.z += bias[col + 2]; v.w += bias[col + 3];
            } else {
                v.x = 1.0f / (1.0f + expf(v.x));
                v.y = 1.0f / (1.0f + expf(v.y));
                v.z = 1.0f / (1.0f + expf(v.z));
                v.w = 1.0f / (1.0f + expf(v.w));
            }
            *(float4*)(Cg + row * N + col) = v;
        }
    }
}

__global__ __launch_bounds__(256) void k_proj(const float* __restrict__ z0,
                                              const float* __restrict__ z1,
                                              const float* __restrict__ z2,
                                              const float* __restrict__ W,
                                              const float* __restrict__ b) {
    const float* zs = (blockIdx.z == 0) ? z0 : ((blockIdx.z == 1) ? z1 : z2);
    gemm_nt(zs, W, g_P[blockIdx.z], b, HF, HD, 0);
}

__global__ __launch_bounds__(256) void k_pair() {
    int p = blockIdx.z;
    int a = (p == 2) ? 1 : 0;     // pairs: (0,1) (0,2) (1,2)
    int b = (p == 0) ? 1 : 2;
    gemm_nt(g_P[a], g_P[b], g_A[p], nullptr, BD, HF, 1);
}

// ============================================================================
// Row L2 normalize of projections: p /= max(||p||, 1e-12)
// ============================================================================
__global__ __launch_bounds__(128) void k_norm() {
    __shared__ float sred[4];
    const int p = blockIdx.y, r = blockIdx.x, tid = threadIdx.x;
    float4* Pr = (float4*)(g_P[p] + (size_t)r * HF);
    float4 v = Pr[tid];
    float s = v.x * v.x + v.y * v.y + v.z * v.z + v.w * v.w;
#pragma unroll
    for (int t = 16; t; t >>= 1) s += __shfl_xor_sync(0xffffffffu, s, t);
    if ((tid & 31) == 0) sred[tid >> 5] = s;
    __syncthreads();
    float tot = sred[0] + sred[1] + sred[2] + sred[3];
    float scl = 1.0f / fmaxf(sqrtf(tot), 1e-12f);
    v.x *= scl; v.y *= scl; v.z *= scl; v.w *= scl;
    Pr[tid] = v;
}

// ============================================================================
// d[i] = (max(sum_j A[i,j], 1e-8))^{-1/2}
// ============================================================================
__global__ __launch_bounds__(256) void k_degree() {
    __shared__ float sred[8];
    const int p = blockIdx.y, r = blockIdx.x, tid = threadIdx.x;
    const float4* Ar = (const float4*)(g_A[p] + (size_t)r * BD);
    float s = 0.f;
#pragma unroll
    for (int q = 0; q < 4; q++) {
        float4 v = Ar[tid + q * 256];
        s += (v.x + v.y) + (v.z + v.w);
    }
#pragma unroll
    for (int t = 16; t; t >>= 1) s += __shfl_xor_sync(0xffffffffu, s, t);
    if ((tid & 31) == 0) sred[tid >> 5] = s;
    __syncthreads();
    if (tid == 0) {
        float tot = 0.f;
        for (int w = 0; w < 8; w++) tot += sred[w];
        g_d[p][r] = 1.0f / sqrtf(fmaxf(tot, 1e-8f));
    }
}

// ============================================================================
// JAX threefry2x32 PRNG — PARTITIONABLE scheme (jax_threefry_partitionable=True,
// the default in modern JAX): per-element 64-bit linear-index counter,
// counter pair = (idx>>32, idx) = (0, e) here; 32-bit output = o0 ^ o1.
// fold_in is unchanged by the flag: threefry_2x32(key, (0, i)).
// ============================================================================
#define TF_R(r) { x0 += x1; x1 = (x1 << (r)) | (x1 >> (32 - (r))); x1 ^= x0; }
__device__ __forceinline__ void tf_hash(unsigned k0, unsigned k1,
                                        unsigned c0, unsigned c1,
                                        unsigned& o0, unsigned& o1) {
    unsigned ks2 = k0 ^ k1 ^ 0x1BD11BDAu;
    unsigned x0 = c0 + k0, x1 = c1 + k1;
    TF_R(13) TF_R(15) TF_R(26) TF_R(6)   x0 += k1;  x1 += ks2 + 1u;
    TF_R(17) TF_R(29) TF_R(16) TF_R(24)  x0 += ks2; x1 += k0  + 2u;
    TF_R(13) TF_R(15) TF_R(26) TF_R(6)   x0 += k0;  x1 += k1  + 3u;
    TF_R(17) TF_R(29) TF_R(16) TF_R(24)  x0 += k1;  x1 += ks2 + 4u;
    TF_R(13) TF_R(15) TF_R(26) TF_R(6)   x0 += ks2; x1 += k0  + 5u;
    o0 = x0; o1 = x1;
}

__device__ __forceinline__ float bits_to_normal(unsigned bits) {
    // uniform [0,1): bitcast((bits>>9)|1.0f) - 1; then affine to [lo, 1), clamp,
    // then sqrt(2)*erfinv. Matches jax.random.normal (f32) bit-for-bit up to
    // erfinv's last-ulp differences.
    float f = __uint_as_float((bits >> 9) | 0x3f800000u) - 1.0f;
    const float lo = -0.99999994f;        // nextafter(-1, 0) in fp32
    const float span = 2.0f;              // fp32(1.0 - lo) rounds to exactly 2.0
    float u = f * span + lo;              // f*2 exact -> FFMA == mul+add here
    u = fmaxf(lo, u);
    return 1.41421356f * erfinvf(u);      // sqrt(2) * erfinv(u)
}

__global__ __launch_bounds__(256) void k_init() {
    int gid = blockIdx.x * 256 + threadIdx.x;
    if (gid >= 3 * 32768) return;
    int p = gid >> 15;                    // pair index (fold_in data)
    int e = gid & 32767;                  // linear element index in (4096, 8)
    unsigned kp0, kp1, o0, o1;
    tf_hash(0u, 42u, 0u, (unsigned)p, kp0, kp1);   // fold_in(key(42), p)
    tf_hash(kp0, kp1, 0u, (unsigned)e, o0, o1);    // counter = (hi, lo) = (0, e)
    g_V[p][e] = bits_to_normal(o0 ^ o1);           // partitionable 32-bit fold
}

// ============================================================================
// Householder QR of 4096x8 panel (LAPACK sgeqr2 + sorg2r conventions),
// one CTA per pair, in place on global buffer. Epilogue: V <- Q, X <- d⊙Q.
// which==0: factor g_V;  which==1: factor g_LV.
// ============================================================================
__global__ __launch_bounds__(1024) void k_qr(int which) {
    const int p = blockIdx.x;
    float* __restrict__ Aw = which ? g_LV[p] : g_V[p];
    const int m = BD;
    const int tid = threadIdx.x;
    const int lane = tid & 31;
    const int wid  = tid >> 5;
    __shared__ float tau[NC];
    __shared__ float red[32][NC];
    __shared__ float sred[32];
    __shared__ float sc[2];                // [0]=1/(alpha-beta), [1]=beta

    // ---------------- factorization (geqr2) ----------------
    for (int j = 0; j < NC; j++) {
        // ||x||^2, x = A[j+1:, j]
        float s = 0.f;
        for (int i = j + 1 + tid; i < m; i += 1024) {
            float v = Aw[i * NC + j];
            s += v * v;
        }
#pragma unroll
        for (int t = 16; t; t >>= 1) s += __shfl_xor_sync(0xffffffffu, s, t);
        __syncthreads();
        if (lane == 0) sred[wid] = s;
        __syncthreads();
        if (tid == 0) {
            float ss = 0.f;
            for (int w = 0; w < 32; w++) ss += sred[w];
            float alpha = Aw[j * NC + j];
            float xn = sqrtf(ss);
            float t_, scal, beta;
            if (xn == 0.f) { beta = alpha; t_ = 0.f; scal = 0.f; }
            else {
                float nrm = sqrtf(alpha * alpha + ss);
                beta = (alpha >= 0.f) ? -nrm : nrm;   // LAPACK sign convention
                t_   = (beta - alpha) / beta;
                scal = 1.0f / (alpha - beta);
            }
            tau[j] = t_;
            sc[0] = scal; sc[1] = beta;
        }
        __syncthreads();
        const float scal = sc[0];
        const float tj   = tau[j];
        for (int i = j + 1 + tid; i < m; i += 1024) Aw[i * NC + j] *= scal;
        __syncthreads();
        // w[k] = v . A[:,k]  for k>j (v[j]=1)
        float w[NC];
#pragma unroll
        for (int k = 0; k < NC; k++) w[k] = 0.f;
        for (int i = j + tid; i < m; i += 1024) {
            float v = (i == j) ? 1.f : Aw[i * NC + j];
#pragma unroll
            for (int k = 0; k < NC; k++)
                if (k > j) w[k] += v * Aw[i * NC + k];
        }
#pragma unroll
        for (int k = 0; k < NC; k++)
#pragma unroll
            for (int t = 16; t; t >>= 1) w[k] += __shfl_xor_sync(0xffffffffu, w[k], t);
        if (lane == 0) {
#pragma unroll
            for (int k = 0; k < NC; k++) red[wid][k] = w[k];
        }
        __syncthreads();
#pragma unroll
        for (int k = 0; k < NC; k++) {
            float t2 = 0.f;
            for (int ww = 0; ww < 32; ww++) t2 += red[ww][k];
            w[k] = t2;
        }
        for (int i = j + tid; i < m; i += 1024) {
            float v = (i == j) ? 1.f : Aw[i * NC + j];
#pragma unroll
            for (int k = 0; k < NC; k++)
                if (k > j) Aw[i * NC + k] -= tj * w[k] * v;
        }
        if (tid == 0) Aw[j * NC + j] = sc[1];   // store beta on diag
        __syncthreads();
    }

    // ---------------- form Q (sorg2r) ----------------
    for (int j = NC - 1; j >= 0; j--) {
        const float tj = tau[j];
        if (j < NC - 1) {
            float w[NC];
#pragma unroll
            for (int k = 0; k < NC; k++) w[k] = 0.f;
            for (int i = j + tid; i < m; i += 1024) {
                float v = (i == j) ? 1.f : Aw[i * NC + j];
#pragma unroll
                for (int k = 0; k < NC; k++)
                    if (k > j) w[k] += v * Aw[i * NC + k];
            }
#pragma unroll
            for (int k = 0; k < NC; k++)
#pragma unroll
                for (int t = 16; t; t >>= 1) w[k] += __shfl_xor_sync(0xffffffffu, w[k], t);
            if (lane == 0) {
#pragma unroll
                for (int k = 0; k < NC; k++) red[wid][k] = w[k];
            }
            __syncthreads();
#pragma unroll
            for (int k = 0; k < NC; k++) {
                float t2 = 0.f;
                for (int ww = 0; ww < 32; ww++) t2 += red[ww][k];
                w[k] = t2;
            }
            for (int i = j + tid; i < m; i += 1024) {
                float v = (i == j) ? 1.f : Aw[i * NC + j];
#pragma unroll
                for (int k = 0; k < NC; k++)
                    if (k > j) Aw[i * NC + k] -= tj * w[k] * v;
            }
            __syncthreads();
        }
        for (int i = tid; i < m; i += 1024) {
            float val;
            if (i < j)       val = 0.f;
            else if (i == j) val = 1.f - tj;
            else             val = -tj * Aw[i * NC + j];
            Aw[i * NC + j] = val;
        }
        __syncthreads();
    }

    // ---------------- epilogue: V <- Q, X <- d⊙Q ----------------
    const float* __restrict__ dv = g_d[p];
    for (int i = tid; i < m * NC; i += 1024) {
        float q = Aw[i];
        g_V[p][i] = q;
        g_X[p][i] = dv[i >> 3] * q;
    }
}

// ============================================================================
// LV[i,:] = V[i,:] - d[i] * (A[i,:] @ X)      X = d ⊙ V (precomputed)
// 8 warps per block, one row per warp; X staged through smem in 512-row chunks.
// ============================================================================
__global__ __launch_bounds__(256) void k_matvec() {
    const int p = blockIdx.y;
    const int warp = threadIdx.x >> 5, lane = threadIdx.x & 31;
    const int row = blockIdx.x * 8 + warp;
    __shared__ float sX[512 * NC];          // 16 KB
    const float* __restrict__ Ar = g_A[p] + (size_t)row * BD;
    const float* __restrict__ Xg = g_X[p];
    float acc[8] = {0, 0, 0, 0, 0, 0, 0, 0};
    for (int t0 = 0; t0 < BD; t0 += 512) {
        __syncthreads();
        for (int i = threadIdx.x; i < 512 * NC / 4; i += 256)
            ((float4*)sX)[i] = ((const float4*)(Xg + t0 * NC))[i];
        __syncthreads();
        for (int t = lane; t < 512; t += 32) {
            float a = Ar[t0 + t];
            float4 x0 = *(const float4*)(sX + t * NC);
            float4 x1 = *(const float4*)(sX + t * NC + 4);
            acc[0] += a * x0.x; acc[1] += a * x0.y;
            acc[2] += a * x0.z; acc[3] += a * x0.w;
            acc[4] += a * x1.x; acc[5] += a * x1.y;
            acc[6] += a * x1.z; acc[7] += a * x1.w;
        }
    }
#pragma unroll
    for (int k = 0; k < 8; k++)
#pragma unroll
        for (int t = 16; t; t >>= 1) acc[k] += __shfl_xor_sync(0xffffffffu, acc[k], t);
    if (lane == 0) {
        float di = g_d[p][row];
#pragma unroll
        for (int k = 0; k < 8; k++)
            g_LV[p][row * NC + k] = g_V[p][row * NC + k] - di * acc[k];
    }
}

// ============================================================================
// out = LayerNorm(GELU(spec @ W_out^T + b_out)) ; spec = concat(V0,V1,V2)
// One block (128 threads) per row; each thread owns 4 outputs.
// ============================================================================
__global__ __launch_bounds__(128) void k_final(const float* __restrict__ Wo,
                                               const float* __restrict__ bo,
                                               const float* __restrict__ lg,
                                               const float* __restrict__ lb,
                                               float* __restrict__ out) {
    const int r = blockIdx.x, tid = threadIdx.x;
    __shared__ float spec[24];
    __shared__ float sred[4];
    if (tid < 24) spec[tid] = g_V[tid >> 3][r * NC + (tid & 7)];
    __syncthreads();
    float x[4];
    float s = 0.f;
#pragma unroll
    for (int q = 0; q < 4; q++) {
        int j = tid + q * 128;
        const float* wr = Wo + j * 24;
        float acc = bo[j];
#pragma unroll
        for (int c = 0; c < 24; c++) acc += spec[c] * wr[c];
        float gl = 0.5f * acc * (1.0f + erff(acc * 0.70710678118654752f));
        x[q] = gl; s += gl;
    }
#pragma unroll
    for (int t = 16; t; t >>= 1) s += __shfl_xor_sync(0xffffffffu, s, t);
    if ((tid & 31) == 0) sred[tid >> 5] = s;
    __syncthreads();
    float mu = (sred[0] + sred[1] + sred[2] + sred[3]) * (1.0f / HF);
    float s2 = 0.f;
#pragma unroll
    for (int q = 0; q < 4; q++) {
        float d = x[q] - mu;
        s2 += d * d;
    }
#pragma unroll
    for (int t = 16; t; t >>= 1) s2 += __shfl_xor_sync(0xffffffffu, s2, t);
    __syncthreads();
    if ((tid & 31) == 0) sred[tid >> 5] = s2;
    __syncthreads();
    float var = (sred[0] + sred[1] + sred[2] + sred[3]) * (1.0f / HF);
    float inv = 1.0f / sqrtf(var + 1e-5f);
#pragma unroll
    for (int q = 0; q < 4; q++) {
        int j = tid + q * 128;
        out[(size_t)r * HF + j] = (x[q] - mu) * inv * lg[j] + lb[j];
    }
}

// ============================================================================
// Launch sequence (graph-capturable: kernel launches on default stream only)
// ============================================================================
extern "C" void kernel_launch(void* const* d_in, const int* in_sizes, int n_in,
                              void* d_out, int out_size) {
    const float* zt = (const float*)d_in[0];
    const float* za = (const float*)d_in[1];
    const float* zf = (const float*)d_in[2];
    const float* Wp = (const float*)d_in[3];
    const float* bp = (const float*)d_in[4];
    const float* Wo = (const float*)d_in[5];
    const float* bo = (const float*)d_in[6];
    const float* lg = (const float*)d_in[7];
    const float* lb = (const float*)d_in[8];
    float* out = (float*)d_out;

    k_proj<<<dim3(HF / 128, BD / 128, 3), 256>>>(zt, za, zf, Wp, bp);
    k_norm<<<dim3(BD, 3), 128>>>();
    k_pair<<<dim3(BD / 128, BD / 128, 3), 256>>>();
    k_degree<<<dim3(BD, 3), 256>>>();
    k_init<<<(3 * 32768 + 255) / 256, 256>>>();
    k_qr<<<3, 1024>>>(0);
    for (int it = 0; it < 5; it++) {
        k_matvec<<<dim3(BD / 8, 3), 256>>>();
        k_qr<<<3, 1024>>>(1);
    }
    k_final<<<BD, 128>>>(Wo, bo, lg, lb, out);
}

// round 9
// speedup vs baseline: 1.2365x; 1.2365x over previous
#include <cuda_runtime.h>
#include <math.h>

// ============================================================================
// SpectralDiscrepancyModule — pipeline with tf32 tensor-core pair GEMM.
// B=4096, H=1024, HALF=512, NCOMP=8, 3 pairs, 5 power-iteration steps.
// ============================================================================

#define BD   4096
#define HD   1024
#define HF   512
#define NC   8

// ------------------------- device scratch (no runtime alloc allowed) -------
__device__ float g_P[3][BD * HF];        // normalized projections   (24 MB)
__device__ float g_A[3][BD * BD];        // 1 - sigmoid(Pa Pb^T)     (192 MB)
__device__ float g_d[3][BD];             // deg^{-1/2}
__device__ float g_V[3][BD * NC];        // current eigvec block (Q)
__device__ float g_X[3][BD * NC];        // d ⊙ V
__device__ float g_LV[3][BD * NC];       // L @ V (QR workspace)

// ============================================================================
// fp32 NT-GEMM (kept for the projection GEMM): C = A B^T + bias
// 128x128x16 tile, 256 threads, 8x8 register microtile.
// ============================================================================
__device__ __forceinline__ void gemm_nt(const float* __restrict__ Ag,
                                        const float* __restrict__ Bg,
                                        float* __restrict__ Cg,
                                        const float* __restrict__ bias,
                                        int N, int K) {
    __shared__ float As[16][128];
    __shared__ float Bs[16][128];
    const int tid  = threadIdx.x;
    const int m0   = blockIdx.y * 128;
    const int n0   = blockIdx.x * 128;
    const int lrow = tid >> 1;
    const int lcol = (tid & 1) << 3;
    const int tm   = (tid >> 4) << 3;
    const int tn   = (tid & 15) << 3;

    float acc[8][8];
#pragma unroll
    for (int i = 0; i < 8; i++)
#pragma unroll
        for (int j = 0; j < 8; j++) acc[i][j] = 0.f;

    const float* Ap = Ag + (size_t)(m0 + lrow) * K + lcol;
    const float* Bp = Bg + (size_t)(n0 + lrow) * K + lcol;

    for (int kt = 0; kt < K; kt += 16) {
        float4 a0 = *(const float4*)(Ap + kt);
        float4 a1 = *(const float4*)(Ap + kt + 4);
        float4 b0 = *(const float4*)(Bp + kt);
        float4 b1 = *(const float4*)(Bp + kt + 4);
        __syncthreads();
        As[lcol + 0][lrow] = a0.x; As[lcol + 1][lrow] = a0.y;
        As[lcol + 2][lrow] = a0.z; As[lcol + 3][lrow] = a0.w;
        As[lcol + 4][lrow] = a1.x; As[lcol + 5][lrow] = a1.y;
        As[lcol + 6][lrow] = a1.z; As[lcol + 7][lrow] = a1.w;
        Bs[lcol + 0][lrow] = b0.x; Bs[lcol + 1][lrow] = b0.y;
        Bs[lcol + 2][lrow] = b0.z; Bs[lcol + 3][lrow] = b0.w;
        Bs[lcol + 4][lrow] = b1.x; Bs[lcol + 5][lrow] = b1.y;
        Bs[lcol + 6][lrow] = b1.z; Bs[lcol + 7][lrow] = b1.w;
        __syncthreads();
#pragma unroll
        for (int k = 0; k < 16; k++) {
            float4 ra0 = *(const float4*)&As[k][tm];
            float4 ra1 = *(const float4*)&As[k][tm + 4];
            float4 rb0 = *(const float4*)&Bs[k][tn];
            float4 rb1 = *(const float4*)&Bs[k][tn + 4];
            float ra[8] = {ra0.x, ra0.y, ra0.z, ra0.w, ra1.x, ra1.y, ra1.z, ra1.w};
            float rb[8] = {rb0.x, rb0.y, rb0.z, rb0.w, rb1.x, rb1.y, rb1.z, rb1.w};
#pragma unroll
            for (int i = 0; i < 8; i++)
#pragma unroll
                for (int j = 0; j < 8; j++) acc[i][j] += ra[i] * rb[j];
        }
    }
#pragma unroll
    for (int i = 0; i < 8; i++) {
        size_t row = (size_t)(m0 + tm + i);
#pragma unroll
        for (int jb = 0; jb < 2; jb++) {
            int col = n0 + tn + jb * 4;
            float4 v;
            v.x = acc[i][jb * 4 + 0] + bias[col + 0];
            v.y = acc[i][jb * 4 + 1] + bias[col + 1];
            v.z = acc[i][jb * 4 + 2] + bias[col + 2];
            v.w = acc[i][jb * 4 + 3] + bias[col + 3];
            *(float4*)(Cg + row * N + col) = v;
        }
    }
}

__global__ __launch_bounds__(256) void k_proj(const float* __restrict__ z0,
                                              const float* __restrict__ z1,
                                              const float* __restrict__ z2,
                                              const float* __restrict__ W,
                                              const float* __restrict__ b) {
    const float* zs = (blockIdx.z == 0) ? z0 : ((blockIdx.z == 1) ? z1 : z2);
    gemm_nt(zs, W, g_P[blockIdx.z], b, HF, HD);
}

// ============================================================================
// 1 - sigmoid(x) = 1/(1+e^x) for |x| <= 1 (guaranteed: rows are unit-norm).
// 0.5 - 0.5*tanh(x/2), tanh via odd Taylor series through y^13 (y=x/2<=0.5):
// abs error <= 3e-8 on [-1,1]. Pure FMA pipe — avoids 50M MUFU ops.
// ============================================================================
__device__ __forceinline__ float one_minus_sigmoid(float x) {
    float u = x * x;
    float q =                8.76984e-7f;
    q = fmaf(q, u,         -8.65551e-6f);
    q = fmaf(q, u,          8.5427532e-5f);
    q = fmaf(q, u,         -8.4325397e-4f);
    q = fmaf(q, u,          8.3333333e-3f);
    q = fmaf(q, u,         -8.3333333e-2f);
    q = fmaf(q, u,          1.0f);
    return fmaf(x * q, -0.25f, 0.5f);
}

// ============================================================================
// tf32 tensor-core pair GEMM: A_p = 1 - sigmoid(Pa Pb^T)
// CTA tile 128x128, 256 thr = 8 warps (2m x 4n), warp tile 64x32.
// mma.sync.m16n8k8 tf32; K-chunk 16, double-buffered smem, row stride 20
// floats (conflict-free fragment LDS). cvt.rna.tf32.f32 at smem store.
// ============================================================================
#define SROW 20                       // smem row stride (floats)

__device__ __forceinline__ void cvst(float* dst, float4 v) {
    uint4 t;
    asm("cvt.rna.tf32.f32 %0, %1;" : "=r"(t.x) : "f"(v.x));
    asm("cvt.rna.tf32.f32 %0, %1;" : "=r"(t.y) : "f"(v.y));
    asm("cvt.rna.tf32.f32 %0, %1;" : "=r"(t.z) : "f"(v.z));
    asm("cvt.rna.tf32.f32 %0, %1;" : "=r"(t.w) : "f"(v.w));
    *(uint4*)dst = t;
}

__device__ __forceinline__ void mma8(float* c, const unsigned* a, const unsigned* b) {
    asm volatile(
        "mma.sync.aligned.m16n8k8.row.col.f32.tf32.tf32.f32 "
        "{%0,%1,%2,%3}, {%4,%5,%6,%7}, {%8,%9}, {%0,%1,%2,%3};"
        : "+f"(c[0]), "+f"(c[1]), "+f"(c[2]), "+f"(c[3])
        : "r"(a[0]), "r"(a[1]), "r"(a[2]), "r"(a[3]), "r"(b[0]), "r"(b[1]));
}

__global__ __launch_bounds__(256) void k_pair_tf32() {
    const int p = blockIdx.z;
    const int pa = (p == 2) ? 1 : 0;       // pairs: (0,1) (0,2) (1,2)
    const int pb = (p == 0) ? 1 : 2;
    const float* __restrict__ Ag = g_P[pa];
    const float* __restrict__ Bg = g_P[pb];
    float* __restrict__ Cg = g_A[p];

    __shared__ float As[2][128 * SROW];
    __shared__ float Bs[2][128 * SROW];

    const int tid  = threadIdx.x;
    const int lane = tid & 31;
    const int wm   = (tid >> 5) >> 2;      // 0..1
    const int wn   = (tid >> 5) & 3;       // 0..3
    const int m0   = blockIdx.y * 128;
    const int n0   = blockIdx.x * 128;

    // global staging: each thread loads 2 float4 per tile per chunk
    const int ldrow = tid >> 2;            // 0..63
    const int ldcol = (tid & 3) << 2;      // 0,4,8,12
    const float* Ap0 = Ag + (size_t)(m0 + ldrow) * HF + ldcol;
    const float* Ap1 = Ap0 + (size_t)64 * HF;
    const float* Bp0 = Bg + (size_t)(n0 + ldrow) * HF + ldcol;
    const float* Bp1 = Bp0 + (size_t)64 * HF;
    const int sst = ldrow * SROW + ldcol;

    float acc[4][4][4];
#pragma unroll
    for (int mt = 0; mt < 4; mt++)
#pragma unroll
        for (int nt = 0; nt < 4; nt++)
#pragma unroll
            for (int i = 0; i < 4; i++) acc[mt][nt][i] = 0.f;

    float4 ca0, ca1, cb0, cb1;
#define LDGC(kt) { ca0 = *(const float4*)(Ap0 + (kt) * 16); \
                   ca1 = *(const float4*)(Ap1 + (kt) * 16); \
                   cb0 = *(const float4*)(Bp0 + (kt) * 16); \
                   cb1 = *(const float4*)(Bp1 + (kt) * 16); }
#define STSC(b)  { cvst(&As[b][sst], ca0); cvst(&As[b][sst + 64 * SROW], ca1); \
                   cvst(&Bs[b][sst], cb0); cvst(&Bs[b][sst + 64 * SROW], cb1); }

    LDGC(0); STSC(0);
    LDGC(1);
    __syncthreads();

    const int arow = (lane >> 2);          // fragment row within 16
    const int acol = (lane & 3);           // fragment k within 4

#pragma unroll 2
    for (int kt = 0; kt < 32; kt++) {
        const int buf = kt & 1;
        if (kt < 31) STSC(buf ^ 1);        // chunk kt+1 (in regs) -> other buffer
        if (kt < 30) LDGC(kt + 2);         // prefetch chunk kt+2
#pragma unroll
        for (int kk = 0; kk < 16; kk += 8) {
            unsigned afr[4][4], bfr[4][2];
#pragma unroll
            for (int mt = 0; mt < 4; mt++) {
                const float* ab = &As[buf][(wm * 64 + mt * 16 + arow) * SROW + kk + acol];
                afr[mt][0] = __float_as_uint(ab[0]);
                afr[mt][1] = __float_as_uint(ab[8 * SROW]);
                afr[mt][2] = __float_as_uint(ab[4]);
                afr[mt][3] = __float_as_uint(ab[8 * SROW + 4]);
            }
#pragma unroll
            for (int nt = 0; nt < 4; nt++) {
                const float* bb = &Bs[buf][(wn * 32 + nt * 8 + arow) * SROW + kk + acol];
                bfr[nt][0] = __float_as_uint(bb[0]);
                bfr[nt][1] = __float_as_uint(bb[4]);
            }
#pragma unroll
            for (int mt = 0; mt < 4; mt++)
#pragma unroll
                for (int nt = 0; nt < 4; nt++)
                    mma8(acc[mt][nt], afr[mt], bfr[nt]);
        }
        __syncthreads();
    }

    // epilogue: A = 1 - sigmoid(acc), coalesced float2 stores
#pragma unroll
    for (int mt = 0; mt < 4; mt++) {
        const int r0 = m0 + wm * 64 + mt * 16 + arow;
#pragma unroll
        for (int nt = 0; nt < 4; nt++) {
            const int c0 = n0 + wn * 32 + nt * 8 + acol * 2;
            float2 v0, v1;
            v0.x = one_minus_sigmoid(acc[mt][nt][0]);
            v0.y = one_minus_sigmoid(acc[mt][nt][1]);
            v1.x = one_minus_sigmoid(acc[mt][nt][2]);
            v1.y = one_minus_sigmoid(acc[mt][nt][3]);
            *(float2*)(Cg + (size_t)r0 * BD + c0)       = v0;
            *(float2*)(Cg + (size_t)(r0 + 8) * BD + c0) = v1;
        }
    }
#undef LDGC
#undef STSC
}

// ============================================================================
// Row L2 normalize of projections: p /= max(||p||, 1e-12)
// ============================================================================
__global__ __launch_bounds__(128) void k_norm() {
    __shared__ float sred[4];
    const int p = blockIdx.y, r = blockIdx.x, tid = threadIdx.x;
    float4* Pr = (float4*)(g_P[p] + (size_t)r * HF);
    float4 v = Pr[tid];
    float s = v.x * v.x + v.y * v.y + v.z * v.z + v.w * v.w;
#pragma unroll
    for (int t = 16; t; t >>= 1) s += __shfl_xor_sync(0xffffffffu, s, t);
    if ((tid & 31) == 0) sred[tid >> 5] = s;
    __syncthreads();
    float tot = sred[0] + sred[1] + sred[2] + sred[3];
    float scl = 1.0f / fmaxf(sqrtf(tot), 1e-12f);
    v.x *= scl; v.y *= scl; v.z *= scl; v.w *= scl;
    Pr[tid] = v;
}

// ============================================================================
// d[i] = (max(sum_j A[i,j], 1e-8))^{-1/2}
// ============================================================================
__global__ __launch_bounds__(256) void k_degree() {
    __shared__ float sred[8];
    const int p = blockIdx.y, r = blockIdx.x, tid = threadIdx.x;
    const float4* Ar = (const float4*)(g_A[p] + (size_t)r * BD);
    float s = 0.f;
#pragma unroll
    for (int q = 0; q < 4; q++) {
        float4 v = Ar[tid + q * 256];
        s += (v.x + v.y) + (v.z + v.w);
    }
#pragma unroll
    for (int t = 16; t; t >>= 1) s += __shfl_xor_sync(0xffffffffu, s, t);
    if ((tid & 31) == 0) sred[tid >> 5] = s;
    __syncthreads();
    if (tid == 0) {
        float tot = 0.f;
        for (int w = 0; w < 8; w++) tot += sred[w];
        g_d[p][r] = 1.0f / sqrtf(fmaxf(tot, 1e-8f));
    }
}

// ============================================================================
// JAX threefry2x32 PRNG — partitionable scheme (modern JAX default):
// per-element 64-bit linear-index counter (0, e); 32-bit output = o0 ^ o1.
// ============================================================================
#define TF_R(r) { x0 += x1; x1 = (x1 << (r)) | (x1 >> (32 - (r))); x1 ^= x0; }
__device__ __forceinline__ void tf_hash(unsigned k0, unsigned k1,
                                        unsigned c0, unsigned c1,
                                        unsigned& o0, unsigned& o1) {
    unsigned ks2 = k0 ^ k1 ^ 0x1BD11BDAu;
    unsigned x0 = c0 + k0, x1 = c1 + k1;
    TF_R(13) TF_R(15) TF_R(26) TF_R(6)   x0 += k1;  x1 += ks2 + 1u;
    TF_R(17) TF_R(29) TF_R(16) TF_R(24)  x0 += ks2; x1 += k0  + 2u;
    TF_R(13) TF_R(15) TF_R(26) TF_R(6)   x0 += k0;  x1 += k1  + 3u;
    TF_R(17) TF_R(29) TF_R(16) TF_R(24)  x0 += k1;  x1 += ks2 + 4u;
    TF_R(13) TF_R(15) TF_R(26) TF_R(6)   x0 += ks2; x1 += k0  + 5u;
    o0 = x0; o1 = x1;
}

__device__ __forceinline__ float bits_to_normal(unsigned bits) {
    float f = __uint_as_float((bits >> 9) | 0x3f800000u) - 1.0f;
    const float lo = -0.99999994f;        // nextafter(-1, 0) in fp32
    float u = f * 2.0f + lo;
    u = fmaxf(lo, u);
    return 1.41421356f * erfinvf(u);
}

__global__ __launch_bounds__(256) void k_init() {
    int gid = blockIdx.x * 256 + threadIdx.x;
    if (gid >= 3 * 32768) return;
    int p = gid >> 15;
    int e = gid & 32767;
    unsigned kp0, kp1, o0, o1;
    tf_hash(0u, 42u, 0u, (unsigned)p, kp0, kp1);   // fold_in(key(42), p)
    tf_hash(kp0, kp1, 0u, (unsigned)e, o0, o1);    // counter = (0, e)
    g_V[p][e] = bits_to_normal(o0 ^ o1);
}

// ============================================================================
// Householder QR of 4096x8 panel (LAPACK sgeqr2 + sorg2r conventions),
// one CTA per pair, in place. Epilogue: V <- Q, X <- d⊙Q.
// ============================================================================
__global__ __launch_bounds__(1024) void k_qr(int which) {
    const int p = blockIdx.x;
    float* __restrict__ Aw = which ? g_LV[p] : g_V[p];
    const int m = BD;
    const int tid = threadIdx.x;
    const int lane = tid & 31;
    const int wid  = tid >> 5;
    __shared__ float tau[NC];
    __shared__ float red[32][NC];
    __shared__ float sred[32];
    __shared__ float sc[2];

    for (int j = 0; j < NC; j++) {
        float s = 0.f;
        for (int i = j + 1 + tid; i < m; i += 1024) {
            float v = Aw[i * NC + j];
            s += v * v;
        }
#pragma unroll
        for (int t = 16; t; t >>= 1) s += __shfl_xor_sync(0xffffffffu, s, t);
        __syncthreads();
        if (lane == 0) sred[wid] = s;
        __syncthreads();
        if (tid == 0) {
            float ss = 0.f;
            for (int w = 0; w < 32; w++) ss += sred[w];
            float alpha = Aw[j * NC + j];
            float t_, scal, beta;
            if (ss == 0.f) { beta = alpha; t_ = 0.f; scal = 0.f; }
            else {
                float nrm = sqrtf(alpha * alpha + ss);
                beta = (alpha >= 0.f) ? -nrm : nrm;
                t_   = (beta - alpha) / beta;
                scal = 1.0f / (alpha - beta);
            }
            tau[j] = t_;
            sc[0] = scal; sc[1] = beta;
        }
        __syncthreads();
        const float scal = sc[0];
        const float tj   = tau[j];
        for (int i = j + 1 + tid; i < m; i += 1024) Aw[i * NC + j] *= scal;
        __syncthreads();
        float w[NC];
#pragma unroll
        for (int k = 0; k < NC; k++) w[k] = 0.f;
        for (int i = j + tid; i < m; i += 1024) {
            float v = (i == j) ? 1.f : Aw[i * NC + j];
#pragma unroll
            for (int k = 0; k < NC; k++)
                if (k > j) w[k] += v * Aw[i * NC + k];
        }
#pragma unroll
        for (int k = 0; k < NC; k++)
#pragma unroll
            for (int t = 16; t; t >>= 1) w[k] += __shfl_xor_sync(0xffffffffu, w[k], t);
        if (lane == 0) {
#pragma unroll
            for (int k = 0; k < NC; k++) red[wid][k] = w[k];
        }
        __syncthreads();
#pragma unroll
        for (int k = 0; k < NC; k++) {
            float t2 = 0.f;
            for (int ww = 0; ww < 32; ww++) t2 += red[ww][k];
            w[k] = t2;
        }
        for (int i = j + tid; i < m; i += 1024) {
            float v = (i == j) ? 1.f : Aw[i * NC + j];
#pragma unroll
            for (int k = 0; k < NC; k++)
                if (k > j) Aw[i * NC + k] -= tj * w[k] * v;
        }
        if (tid == 0) Aw[j * NC + j] = sc[1];
        __syncthreads();
    }

    for (int j = NC - 1; j >= 0; j--) {
        const float tj = tau[j];
        if (j < NC - 1) {
            float w[NC];
#pragma unroll
            for (int k = 0; k < NC; k++) w[k] = 0.f;
            for (int i = j + tid; i < m; i += 1024) {
                float v = (i == j) ? 1.f : Aw[i * NC + j];
#pragma unroll
                for (int k = 0; k < NC; k++)
                    if (k > j) w[k] += v * Aw[i * NC + k];
            }
#pragma unroll
            for (int k = 0; k < NC; k++)
#pragma unroll
                for (int t = 16; t; t >>= 1) w[k] += __shfl_xor_sync(0xffffffffu, w[k], t);
            if (lane == 0) {
#pragma unroll
                for (int k = 0; k < NC; k++) red[wid][k] = w[k];
            }
            __syncthreads();
#pragma unroll
            for (int k = 0; k < NC; k++) {
                float t2 = 0.f;
                for (int ww = 0; ww < 32; ww++) t2 += red[ww][k];
                w[k] = t2;
            }
            for (int i = j + tid; i < m; i += 1024) {
                float v = (i == j) ? 1.f : Aw[i * NC + j];
#pragma unroll
                for (int k = 0; k < NC; k++)
                    if (k > j) Aw[i * NC + k] -= tj * w[k] * v;
            }
            __syncthreads();
        }
        for (int i = tid; i < m; i += 1024) {
            float val;
            if (i < j)       val = 0.f;
            else if (i == j) val = 1.f - tj;
            else             val = -tj * Aw[i * NC + j];
            Aw[i * NC + j] = val;
        }
        __syncthreads();
    }

    const float* __restrict__ dv = g_d[p];
    for (int i = tid; i < m * NC; i += 1024) {
        float q = Aw[i];
        g_V[p][i] = q;
        g_X[p][i] = dv[i >> 3] * q;
    }
}

// ============================================================================
// LV[i,:] = V[i,:] - d[i] * (A[i,:] @ X)
// ============================================================================
__global__ __launch_bounds__(256) void k_matvec() {
    const int p = blockIdx.y;
    const int warp = threadIdx.x >> 5, lane = threadIdx.x & 31;
    const int row = blockIdx.x * 8 + warp;
    __shared__ float sX[512 * NC];
    const float* __restrict__ Ar = g_A[p] + (size_t)row * BD;
    const float* __restrict__ Xg = g_X[p];
    float acc[8] = {0, 0, 0, 0, 0, 0, 0, 0};
    for (int t0 = 0; t0 < BD; t0 += 512) {
        __syncthreads();
        for (int i = threadIdx.x; i < 512 * NC / 4; i += 256)
            ((float4*)sX)[i] = ((const float4*)(Xg + t0 * NC))[i];
        __syncthreads();
        for (int t = lane; t < 512; t += 32) {
            float a = Ar[t0 + t];
            float4 x0 = *(const float4*)(sX + t * NC);
            float4 x1 = *(const float4*)(sX + t * NC + 4);
            acc[0] += a * x0.x; acc[1] += a * x0.y;
            acc[2] += a * x0.z; acc[3] += a * x0.w;
            acc[4] += a * x1.x; acc[5] += a * x1.y;
            acc[6] += a * x1.z; acc[7] += a * x1.w;
        }
    }
#pragma unroll
    for (int k = 0; k < 8; k++)
#pragma unroll
        for (int t = 16; t; t >>= 1) acc[k] += __shfl_xor_sync(0xffffffffu, acc[k], t);
    if (lane == 0) {
        float di = g_d[p][row];
#pragma unroll
        for (int k = 0; k < 8; k++)
            g_LV[p][row * NC + k] = g_V[p][row * NC + k] - di * acc[k];
    }
}

// ============================================================================
// out = LayerNorm(GELU(spec @ W_out^T + b_out)) ; spec = concat(V0,V1,V2)
// ============================================================================
__global__ __launch_bounds__(128) void k_final(const float* __restrict__ Wo,
                                               const float* __restrict__ bo,
                                               const float* __restrict__ lg,
                                               const float* __restrict__ lb,
                                               float* __restrict__ out) {
    const int r = blockIdx.x, tid = threadIdx.x;
    __shared__ float spec[24];
    __shared__ float sred[4];
    if (tid < 24) spec[tid] = g_V[tid >> 3][r * NC + (tid & 7)];
    __syncthreads();
    float x[4];
    float s = 0.f;
#pragma unroll
    for (int q = 0; q < 4; q++) {
        int j = tid + q * 128;
        const float* wr = Wo + j * 24;
        float acc = bo[j];
#pragma unroll
        for (int c = 0; c < 24; c++) acc += spec[c] * wr[c];
        float gl = 0.5f * acc * (1.0f + erff(acc * 0.70710678118654752f));
        x[q] = gl; s += gl;
    }
#pragma unroll
    for (int t = 16; t; t >>= 1) s += __shfl_xor_sync(0xffffffffu, s, t);
    if ((tid & 31) == 0) sred[tid >> 5] = s;
    __syncthreads();
    float mu = (sred[0] + sred[1] + sred[2] + sred[3]) * (1.0f / HF);
    float s2 = 0.f;
#pragma unroll
    for (int q = 0; q < 4; q++) {
        float d = x[q] - mu;
        s2 += d * d;
    }
#pragma unroll
    for (int t = 16; t; t >>= 1) s2 += __shfl_xor_sync(0xffffffffu, s2, t);
    __syncthreads();
    if ((tid & 31) == 0) sred[tid >> 5] = s2;
    __syncthreads();
    float var = (sred[0] + sred[1] + sred[2] + sred[3]) * (1.0f / HF);
    float inv = 1.0f / sqrtf(var + 1e-5f);
#pragma unroll
    for (int q = 0; q < 4; q++) {
        int j = tid + q * 128;
        out[(size_t)r * HF + j] = (x[q] - mu) * inv * lg[j] + lb[j];
    }
}

// ============================================================================
// Launch sequence (graph-capturable)
// ============================================================================
extern "C" void kernel_launch(void* const* d_in, const int* in_sizes, int n_in,
                              void* d_out, int out_size) {
    const float* zt = (const float*)d_in[0];
    const float* za = (const float*)d_in[1];
    const float* zf = (const float*)d_in[2];
    const float* Wp = (const float*)d_in[3];
    const float* bp = (const float*)d_in[4];
    const float* Wo = (const float*)d_in[5];
    const float* bo = (const float*)d_in[6];
    const float* lg = (const float*)d_in[7];
    const float* lb = (const float*)d_in[8];
    float* out = (float*)d_out;

    k_proj<<<dim3(HF / 128, BD / 128, 3), 256>>>(zt, za, zf, Wp, bp);
    k_norm<<<dim3(BD, 3), 128>>>();
    k_pair_tf32<<<dim3(BD / 128, BD / 128, 3), 256>>>();
    k_degree<<<dim3(BD, 3), 256>>>();
    k_init<<<(3 * 32768 + 255) / 256, 256>>>();
    k_qr<<<3, 1024>>>(0);
    for (int it = 0; it < 5; it++) {
        k_matvec<<<dim3(BD / 8, 3), 256>>>();
        k_qr<<<3, 1024>>>(1);
    }
    k_final<<<BD, 128>>>(Wo, bo, lg, lb, out);
}

// round 10
// speedup vs baseline: 2.0639x; 1.6691x over previous
#include <cuda_runtime.h>
#include <math.h>

// ============================================================================
// SpectralDiscrepancyModule — tf32 tensor GEMMs + smem-resident Householder QR.
// B=4096, H=1024, HALF=512, NCOMP=8, 3 pairs, 5 power-iteration steps.
// ============================================================================

#define BD   4096
#define HD   1024
#define HF   512
#define NC   8

// ------------------------- device scratch (no runtime alloc allowed) -------
__device__ float g_P[3][BD * HF];        // normalized projections   (24 MB)
__device__ float g_A[3][BD * BD];        // 1 - sigmoid(Pa Pb^T)     (192 MB)
__device__ float g_d[3][BD];             // deg^{-1/2}
__device__ float g_V[3][BD * NC];        // current eigvec block (Q)
__device__ float g_X[3][BD * NC];        // d ⊙ V
__device__ float g_LV[3][BD * NC];       // L @ V (QR workspace)

// ============================================================================
// 1 - sigmoid(x) = 1/(1+e^x) for |x| <= 1 (rows are unit-norm -> |dot|<=1).
// Odd tanh Taylor series; abs err <= 3e-8 on [-1,1]. FMA pipe only (no MUFU).
// ============================================================================
__device__ __forceinline__ float one_minus_sigmoid(float x) {
    float u = x * x;
    float q =                8.76984e-7f;
    q = fmaf(q, u,         -8.65551e-6f);
    q = fmaf(q, u,          8.5427532e-5f);
    q = fmaf(q, u,         -8.4325397e-4f);
    q = fmaf(q, u,          8.3333333e-3f);
    q = fmaf(q, u,         -8.3333333e-2f);
    q = fmaf(q, u,          1.0f);
    return fmaf(x * q, -0.25f, 0.5f);
}

// ============================================================================
// tf32 tensor-core NT-GEMM core: C[i,j] = sum_k A[i,k]*B[j,k]
// CTA tile 128x128, 256 thr = 8 warps (2m x 4n), warp tile 64x32.
// mma.sync.m16n8k8 tf32; K-chunk 16, double-buffered smem, row stride 20
// floats (conflict-free fragment LDS). cvt.rna.tf32.f32 at smem store.
// mode 0: C += bias[j] (fp32 out);   mode 1: C = 1 - sigmoid(C)
// ============================================================================
#define SROW 20                       // smem row stride (floats)

__device__ __forceinline__ void cvst(float* dst, float4 v) {
    uint4 t;
    asm("cvt.rna.tf32.f32 %0, %1;" : "=r"(t.x) : "f"(v.x));
    asm("cvt.rna.tf32.f32 %0, %1;" : "=r"(t.y) : "f"(v.y));
    asm("cvt.rna.tf32.f32 %0, %1;" : "=r"(t.z) : "f"(v.z));
    asm("cvt.rna.tf32.f32 %0, %1;" : "=r"(t.w) : "f"(v.w));
    *(uint4*)dst = t;
}

__device__ __forceinline__ void mma8(float* c, const unsigned* a, const unsigned* b) {
    asm volatile(
        "mma.sync.aligned.m16n8k8.row.col.f32.tf32.tf32.f32 "
        "{%0,%1,%2,%3}, {%4,%5,%6,%7}, {%8,%9}, {%0,%1,%2,%3};"
        : "+f"(c[0]), "+f"(c[1]), "+f"(c[2]), "+f"(c[3])
        : "r"(a[0]), "r"(a[1]), "r"(a[2]), "r"(a[3]), "r"(b[0]), "r"(b[1]));
}

__device__ __forceinline__ void gemm_tf32(const float* __restrict__ Ag,
                                          const float* __restrict__ Bg,
                                          float* __restrict__ Cg,
                                          const float* __restrict__ bias,
                                          int lda, int ldc, int nchunk, int mode) {
    __shared__ float As[2][128 * SROW];
    __shared__ float Bs[2][128 * SROW];

    const int tid  = threadIdx.x;
    const int lane = tid & 31;
    const int wm   = (tid >> 5) >> 2;      // 0..1
    const int wn   = (tid >> 5) & 3;       // 0..3
    const int m0   = blockIdx.y * 128;
    const int n0   = blockIdx.x * 128;

    const int ldrow = tid >> 2;            // 0..63
    const int ldcol = (tid & 3) << 2;      // 0,4,8,12
    const float* Ap0 = Ag + (size_t)(m0 + ldrow) * lda + ldcol;
    const float* Ap1 = Ap0 + (size_t)64 * lda;
    const float* Bp0 = Bg + (size_t)(n0 + ldrow) * lda + ldcol;
    const float* Bp1 = Bp0 + (size_t)64 * lda;
    const int sst = ldrow * SROW + ldcol;

    float acc[4][4][4];
#pragma unroll
    for (int mt = 0; mt < 4; mt++)
#pragma unroll
        for (int nt = 0; nt < 4; nt++)
#pragma unroll
            for (int i = 0; i < 4; i++) acc[mt][nt][i] = 0.f;

    float4 ca0, ca1, cb0, cb1;
#define LDGC(kt) { ca0 = *(const float4*)(Ap0 + (kt) * 16); \
                   ca1 = *(const float4*)(Ap1 + (kt) * 16); \
                   cb0 = *(const float4*)(Bp0 + (kt) * 16); \
                   cb1 = *(const float4*)(Bp1 + (kt) * 16); }
#define STSC(b)  { cvst(&As[b][sst], ca0); cvst(&As[b][sst + 64 * SROW], ca1); \
                   cvst(&Bs[b][sst], cb0); cvst(&Bs[b][sst + 64 * SROW], cb1); }

    LDGC(0); STSC(0);
    LDGC(1);
    __syncthreads();

    const int arow = (lane >> 2);
    const int acol = (lane & 3);

#pragma unroll 2
    for (int kt = 0; kt < nchunk; kt++) {
        const int buf = kt & 1;
        if (kt < nchunk - 1) STSC(buf ^ 1);
        if (kt < nchunk - 2) LDGC(kt + 2);
#pragma unroll
        for (int kk = 0; kk < 16; kk += 8) {
            unsigned afr[4][4], bfr[4][2];
#pragma unroll
            for (int mt = 0; mt < 4; mt++) {
                const float* ab = &As[buf][(wm * 64 + mt * 16 + arow) * SROW + kk + acol];
                afr[mt][0] = __float_as_uint(ab[0]);
                afr[mt][1] = __float_as_uint(ab[8 * SROW]);
                afr[mt][2] = __float_as_uint(ab[4]);
                afr[mt][3] = __float_as_uint(ab[8 * SROW + 4]);
            }
#pragma unroll
            for (int nt = 0; nt < 4; nt++) {
                const float* bb = &Bs[buf][(wn * 32 + nt * 8 + arow) * SROW + kk + acol];
                bfr[nt][0] = __float_as_uint(bb[0]);
                bfr[nt][1] = __float_as_uint(bb[4]);
            }
#pragma unroll
            for (int mt = 0; mt < 4; mt++)
#pragma unroll
                for (int nt = 0; nt < 4; nt++)
                    mma8(acc[mt][nt], afr[mt], bfr[nt]);
        }
        __syncthreads();
    }

#pragma unroll
    for (int mt = 0; mt < 4; mt++) {
        const int r0 = m0 + wm * 64 + mt * 16 + arow;
#pragma unroll
        for (int nt = 0; nt < 4; nt++) {
            const int c0 = n0 + wn * 32 + nt * 8 + acol * 2;
            float2 v0, v1;
            if (mode == 0) {
                float b0 = bias[c0], b1 = bias[c0 + 1];
                v0.x = acc[mt][nt][0] + b0; v0.y = acc[mt][nt][1] + b1;
                v1.x = acc[mt][nt][2] + b0; v1.y = acc[mt][nt][3] + b1;
            } else {
                v0.x = one_minus_sigmoid(acc[mt][nt][0]);
                v0.y = one_minus_sigmoid(acc[mt][nt][1]);
                v1.x = one_minus_sigmoid(acc[mt][nt][2]);
                v1.y = one_minus_sigmoid(acc[mt][nt][3]);
            }
            *(float2*)(Cg + (size_t)r0 * ldc + c0)       = v0;
            *(float2*)(Cg + (size_t)(r0 + 8) * ldc + c0) = v1;
        }
    }
#undef LDGC
#undef STSC
}

__global__ __launch_bounds__(256) void k_proj_tf32(const float* __restrict__ z0,
                                                   const float* __restrict__ z1,
                                                   const float* __restrict__ z2,
                                                   const float* __restrict__ W,
                                                   const float* __restrict__ b) {
    const float* zs = (blockIdx.z == 0) ? z0 : ((blockIdx.z == 1) ? z1 : z2);
    gemm_tf32(zs, W, g_P[blockIdx.z], b, HD, HF, HD / 16, 0);
}

__global__ __launch_bounds__(256) void k_pair_tf32() {
    const int p = blockIdx.z;
    const int pa = (p == 2) ? 1 : 0;       // pairs: (0,1) (0,2) (1,2)
    const int pb = (p == 0) ? 1 : 2;
    gemm_tf32(g_P[pa], g_P[pb], g_A[p], nullptr, HF, BD, HF / 16, 1);
}

// ============================================================================
// Row L2 normalize of projections: p /= max(||p||, 1e-12)
// ============================================================================
__global__ __launch_bounds__(128) void k_norm() {
    __shared__ float sred[4];
    const int p = blockIdx.y, r = blockIdx.x, tid = threadIdx.x;
    float4* Pr = (float4*)(g_P[p] + (size_t)r * HF);
    float4 v = Pr[tid];
    float s = v.x * v.x + v.y * v.y + v.z * v.z + v.w * v.w;
#pragma unroll
    for (int t = 16; t; t >>= 1) s += __shfl_xor_sync(0xffffffffu, s, t);
    if ((tid & 31) == 0) sred[tid >> 5] = s;
    __syncthreads();
    float tot = sred[0] + sred[1] + sred[2] + sred[3];
    float scl = 1.0f / fmaxf(sqrtf(tot), 1e-12f);
    v.x *= scl; v.y *= scl; v.z *= scl; v.w *= scl;
    Pr[tid] = v;
}

// ============================================================================
// d[i] = (max(sum_j A[i,j], 1e-8))^{-1/2}
// ============================================================================
__global__ __launch_bounds__(256) void k_degree() {
    __shared__ float sred[8];
    const int p = blockIdx.y, r = blockIdx.x, tid = threadIdx.x;
    const float4* Ar = (const float4*)(g_A[p] + (size_t)r * BD);
    float s = 0.f;
#pragma unroll
    for (int q = 0; q < 4; q++) {
        float4 v = Ar[tid + q * 256];
        s += (v.x + v.y) + (v.z + v.w);
    }
#pragma unroll
    for (int t = 16; t; t >>= 1) s += __shfl_xor_sync(0xffffffffu, s, t);
    if ((tid & 31) == 0) sred[tid >> 5] = s;
    __syncthreads();
    if (tid == 0) {
        float tot = 0.f;
        for (int w = 0; w < 8; w++) tot += sred[w];
        g_d[p][r] = 1.0f / sqrtf(fmaxf(tot, 1e-8f));
    }
}

// ============================================================================
// JAX threefry2x32 PRNG — partitionable scheme (modern JAX default):
// per-element 64-bit linear-index counter (0, e); 32-bit output = o0 ^ o1.
// ============================================================================
#define TF_R(r) { x0 += x1; x1 = (x1 << (r)) | (x1 >> (32 - (r))); x1 ^= x0; }
__device__ __forceinline__ void tf_hash(unsigned k0, unsigned k1,
                                        unsigned c0, unsigned c1,
                                        unsigned& o0, unsigned& o1) {
    unsigned ks2 = k0 ^ k1 ^ 0x1BD11BDAu;
    unsigned x0 = c0 + k0, x1 = c1 + k1;
    TF_R(13) TF_R(15) TF_R(26) TF_R(6)   x0 += k1;  x1 += ks2 + 1u;
    TF_R(17) TF_R(29) TF_R(16) TF_R(24)  x0 += ks2; x1 += k0  + 2u;
    TF_R(13) TF_R(15) TF_R(26) TF_R(6)   x0 += k0;  x1 += k1  + 3u;
    TF_R(17) TF_R(29) TF_R(16) TF_R(24)  x0 += k1;  x1 += ks2 + 4u;
    TF_R(13) TF_R(15) TF_R(26) TF_R(6)   x0 += ks2; x1 += k0  + 5u;
    o0 = x0; o1 = x1;
}

__device__ __forceinline__ float bits_to_normal(unsigned bits) {
    float f = __uint_as_float((bits >> 9) | 0x3f800000u) - 1.0f;
    const float lo = -0.99999994f;        // nextafter(-1, 0) in fp32
    float u = f * 2.0f + lo;
    u = fmaxf(lo, u);
    return 1.41421356f * erfinvf(u);
}

__global__ __launch_bounds__(256) void k_init() {
    int gid = blockIdx.x * 256 + threadIdx.x;
    if (gid >= 3 * 32768) return;
    int p = gid >> 15;
    int e = gid & 32767;
    unsigned kp0, kp1, o0, o1;
    tf_hash(0u, 42u, 0u, (unsigned)p, kp0, kp1);   // fold_in(key(42), p)
    tf_hash(kp0, kp1, 0u, (unsigned)e, o0, o1);    // counter = (0, e)
    g_V[p][e] = bits_to_normal(o0 ^ o1);
}

// ============================================================================
// Householder QR of 4096x8 panel, SMEM-RESIDENT (column-major, 128 KB dynamic
// smem). LAPACK sgeqr2 + sorg2r conventions; one CTA per pair.
// Scale pass fused into dot pass. Epilogue: V <- Q, X <- d⊙Q.
// which==0: factor g_V;  which==1: factor g_LV.
// ============================================================================
#define SH(k, i) sh[(k) * BD + (i)]

__global__ __launch_bounds__(1024) void k_qr(int which) {
    extern __shared__ float sh[];          // [NC][BD] column-major panel
    const int p = blockIdx.x;
    float* __restrict__ Aw = which ? g_LV[p] : g_V[p];
    const int m = BD;
    const int tid = threadIdx.x;
    const int lane = tid & 31;
    const int wid  = tid >> 5;
    __shared__ float tau[NC];
    __shared__ float red[32][NC];
    __shared__ float sred[32];
    __shared__ float sc[2];                // [0]=1/(alpha-beta), [1]=beta

    // ---- load panel (row-major global -> column-major smem), coalesced LDG
    for (int i = tid; i < m * NC; i += 1024)
        SH(i & 7, i >> 3) = Aw[i];
    __syncthreads();

    // ---------------- factorization (geqr2) ----------------
    for (int j = 0; j < NC; j++) {
        float s = 0.f;
        for (int i = j + 1 + tid; i < m; i += 1024) {
            float v = SH(j, i);
            s += v * v;
        }
#pragma unroll
        for (int t = 16; t; t >>= 1) s += __shfl_xor_sync(0xffffffffu, s, t);
        __syncthreads();
        if (lane == 0) sred[wid] = s;
        __syncthreads();
        if (tid == 0) {
            float ss = 0.f;
            for (int w = 0; w < 32; w++) ss += sred[w];
            float alpha = SH(j, j);
            float t_, scal, beta;
            if (ss == 0.f) { beta = alpha; t_ = 0.f; scal = 0.f; }
            else {
                float nrm = sqrtf(alpha * alpha + ss);
                beta = (alpha >= 0.f) ? -nrm : nrm;   // LAPACK sign convention
                t_   = (beta - alpha) / beta;
                scal = 1.0f / (alpha - beta);
            }
            tau[j] = t_;
            sc[0] = scal; sc[1] = beta;
        }
        __syncthreads();
        const float scal = sc[0];
        const float tj   = tau[j];
        // fused scale + dot pass: v_i = scal*col_j (i>j), v_j = 1; write scaled
        float w[NC];
#pragma unroll
        for (int k = 0; k < NC; k++) w[k] = 0.f;
        for (int i = j + tid; i < m; i += 1024) {
            float v;
            if (i == j) v = 1.f;
            else { v = SH(j, i) * scal; SH(j, i) = v; }
#pragma unroll
            for (int k = 0; k < NC; k++)
                if (k > j) w[k] += v * SH(k, i);
        }
#pragma unroll
        for (int k = 0; k < NC; k++)
#pragma unroll
            for (int t = 16; t; t >>= 1) w[k] += __shfl_xor_sync(0xffffffffu, w[k], t);
        if (lane == 0) {
#pragma unroll
            for (int k = 0; k < NC; k++) red[wid][k] = w[k];
        }
        __syncthreads();
#pragma unroll
        for (int k = 0; k < NC; k++) {
            float t2 = 0.f;
            for (int ww = 0; ww < 32; ww++) t2 += red[ww][k];
            w[k] = t2;
        }
        for (int i = j + tid; i < m; i += 1024) {
            float v = (i == j) ? 1.f : SH(j, i);
#pragma unroll
            for (int k = 0; k < NC; k++)
                if (k > j) SH(k, i) -= tj * w[k] * v;
        }
        if (tid == 0) SH(j, j) = sc[1];    // store beta on diag
        __syncthreads();
    }

    // ---------------- form Q (sorg2r) ----------------
    for (int j = NC - 1; j >= 0; j--) {
        const float tj = tau[j];
        if (j < NC - 1) {
            float w[NC];
#pragma unroll
            for (int k = 0; k < NC; k++) w[k] = 0.f;
            for (int i = j + tid; i < m; i += 1024) {
                float v = (i == j) ? 1.f : SH(j, i);
#pragma unroll
                for (int k = 0; k < NC; k++)
                    if (k > j) w[k] += v * SH(k, i);
            }
#pragma unroll
            for (int k = 0; k < NC; k++)
#pragma unroll
                for (int t = 16; t; t >>= 1) w[k] += __shfl_xor_sync(0xffffffffu, w[k], t);
            if (lane == 0) {
#pragma unroll
                for (int k = 0; k < NC; k++) red[wid][k] = w[k];
            }
            __syncthreads();
#pragma unroll
            for (int k = 0; k < NC; k++) {
                float t2 = 0.f;
                for (int ww = 0; ww < 32; ww++) t2 += red[ww][k];
                w[k] = t2;
            }
            for (int i = j + tid; i < m; i += 1024) {
                float v = (i == j) ? 1.f : SH(j, i);
#pragma unroll
                for (int k = 0; k < NC; k++)
                    if (k > j) SH(k, i) -= tj * w[k] * v;
            }
            __syncthreads();
        }
        for (int i = tid; i < m; i += 1024) {
            float val;
            if (i < j)       val = 0.f;
            else if (i == j) val = 1.f - tj;
            else             val = -tj * SH(j, i);
            SH(j, i) = val;
        }
        __syncthreads();
    }

    // ---------------- epilogue: V <- Q, X <- d⊙Q (coalesced STG) ----------
    const float* __restrict__ dv = g_d[p];
    for (int i = tid; i < m * NC; i += 1024) {
        float q = SH(i & 7, i >> 3);
        g_V[p][i] = q;
        g_X[p][i] = dv[i >> 3] * q;
    }
}

// ============================================================================
// LV[i,:] = V[i,:] - d[i] * (A[i,:] @ X)      X = d ⊙ V (precomputed)
// ============================================================================
__global__ __launch_bounds__(256) void k_matvec() {
    const int p = blockIdx.y;
    const int warp = threadIdx.x >> 5, lane = threadIdx.x & 31;
    const int row = blockIdx.x * 8 + warp;
    __shared__ float sX[512 * NC];
    const float* __restrict__ Ar = g_A[p] + (size_t)row * BD;
    const float* __restrict__ Xg = g_X[p];
    float acc[8] = {0, 0, 0, 0, 0, 0, 0, 0};
    for (int t0 = 0; t0 < BD; t0 += 512) {
        __syncthreads();
        for (int i = threadIdx.x; i < 512 * NC / 4; i += 256)
            ((float4*)sX)[i] = ((const float4*)(Xg + t0 * NC))[i];
        __syncthreads();
        for (int t = lane; t < 512; t += 32) {
            float a = Ar[t0 + t];
            float4 x0 = *(const float4*)(sX + t * NC);
            float4 x1 = *(const float4*)(sX + t * NC + 4);
            acc[0] += a * x0.x; acc[1] += a * x0.y;
            acc[2] += a * x0.z; acc[3] += a * x0.w;
            acc[4] += a * x1.x; acc[5] += a * x1.y;
            acc[6] += a * x1.z; acc[7] += a * x1.w;
        }
    }
#pragma unroll
    for (int k = 0; k < 8; k++)
#pragma unroll
        for (int t = 16; t; t >>= 1) acc[k] += __shfl_xor_sync(0xffffffffu, acc[k], t);
    if (lane == 0) {
        float di = g_d[p][row];
#pragma unroll
        for (int k = 0; k < 8; k++)
            g_LV[p][row * NC + k] = g_V[p][row * NC + k] - di * acc[k];
    }
}

// ============================================================================
// out = LayerNorm(GELU(spec @ W_out^T + b_out)) ; spec = concat(V0,V1,V2)
// ============================================================================
__global__ __launch_bounds__(128) void k_final(const float* __restrict__ Wo,
                                               const float* __restrict__ bo,
                                               const float* __restrict__ lg,
                                               const float* __restrict__ lb,
                                               float* __restrict__ out) {
    const int r = blockIdx.x, tid = threadIdx.x;
    __shared__ float spec[24];
    __shared__ float sred[4];
    if (tid < 24) spec[tid] = g_V[tid >> 3][r * NC + (tid & 7)];
    __syncthreads();
    float x[4];
    float s = 0.f;
#pragma unroll
    for (int q = 0; q < 4; q++) {
        int j = tid + q * 128;
        const float* wr = Wo + j * 24;
        float acc = bo[j];
#pragma unroll
        for (int c = 0; c < 24; c++) acc += spec[c] * wr[c];
        float gl = 0.5f * acc * (1.0f + erff(acc * 0.70710678118654752f));
        x[q] = gl; s += gl;
    }
#pragma unroll
    for (int t = 16; t; t >>= 1) s += __shfl_xor_sync(0xffffffffu, s, t);
    if ((tid & 31) == 0) sred[tid >> 5] = s;
    __syncthreads();
    float mu = (sred[0] + sred[1] + sred[2] + sred[3]) * (1.0f / HF);
    float s2 = 0.f;
#pragma unroll
    for (int q = 0; q < 4; q++) {
        float d = x[q] - mu;
        s2 += d * d;
    }
#pragma unroll
    for (int t = 16; t; t >>= 1) s2 += __shfl_xor_sync(0xffffffffu, s2, t);
    __syncthreads();
    if ((tid & 31) == 0) sred[tid >> 5] = s2;
    __syncthreads();
    float var = (sred[0] + sred[1] + sred[2] + sred[3]) * (1.0f / HF);
    float inv = 1.0f / sqrtf(var + 1e-5f);
#pragma unroll
    for (int q = 0; q < 4; q++) {
        int j = tid + q * 128;
        out[(size_t)r * HF + j] = (x[q] - mu) * inv * lg[j] + lb[j];
    }
}

// ============================================================================
// Launch sequence (graph-capturable)
// ============================================================================
extern "C" void kernel_launch(void* const* d_in, const int* in_sizes, int n_in,
                              void* d_out, int out_size) {
    const float* zt = (const float*)d_in[0];
    const float* za = (const float*)d_in[1];
    const float* zf = (const float*)d_in[2];
    const float* Wp = (const float*)d_in[3];
    const float* bp = (const float*)d_in[4];
    const float* Wo = (const float*)d_in[5];
    const float* bo = (const float*)d_in[6];
    const float* lg = (const float*)d_in[7];
    const float* lb = (const float*)d_in[8];
    float* out = (float*)d_out;

    const int QR_SMEM = BD * NC * sizeof(float);   // 128 KB dynamic smem
    cudaFuncSetAttribute(k_qr, cudaFuncAttributeMaxDynamicSharedMemorySize, QR_SMEM);

    k_proj_tf32<<<dim3(HF / 128, BD / 128, 3), 256>>>(zt, za, zf, Wp, bp);
    k_norm<<<dim3(BD, 3), 128>>>();
    k_pair_tf32<<<dim3(BD / 128, BD / 128, 3), 256>>>();
    k_degree<<<dim3(BD, 3), 256>>>();
    k_init<<<(3 * 32768 + 255) / 256, 256>>>();
    k_qr<<<3, 1024, QR_SMEM>>>(0);
    for (int it = 0; it < 5; it++) {
        k_matvec<<<dim3(BD / 8, 3), 256>>>();
        k_qr<<<3, 1024, QR_SMEM>>>(1);
    }
    k_final<<<BD, 128>>>(Wo, bo, lg, lb, out);
}